// round 13
// baseline (speedup 1.0000x reference)
#include <cuda_runtime.h>
#include <math.h>

#define BB 8
#define SS 256
#define HH 100
#define PP 20
#define EPSF 1e-8f
#define NEGF 1e30f
typedef unsigned long long ull;

__device__ __forceinline__ ull pk2(float lo, float hi) {
    ull r; asm("mov.b64 %0, {%1,%2};" : "=l"(r) : "f"(lo), "f"(hi)); return r;
}
__device__ __forceinline__ void unpk2(ull v, float& lo, float& hi) {
    asm("mov.b64 {%0,%1}, %2;" : "=f"(lo), "=f"(hi) : "l"(v));
}
__device__ __forceinline__ ull fma2_(ull a, ull b, ull c) {
    ull d; asm("fma.rn.f32x2 %0, %1, %2, %3;" : "=l"(d) : "l"(a), "l"(b), "l"(c)); return d;
}

// ---------------- scratch -----------------------------------------------------
__device__ float g_c[2][BB][SS][HH];
__device__ float g_cT[2][BB][HH][SS];
__device__ float g_norm[2][BB][SS];
__device__ float g_npw[2][BB][SS][4 * PP];
__device__ float g_w2[4][PP][HH];
__device__ float g_last[2][BB][HH];
__device__ float g_nlast[2][BB];
__device__ float g_nlastw[2][BB][PP];
__device__ float g_len[2][BB];
__device__ float g_cos[BB][SS][SS];
__device__ float g_cosT[BB][SS][SS];
__device__ float g_cmax[2][BB][SS];
__device__ float g_cmean[2][BB][SS];
__device__ float g_csum[2][BB][SS];
__device__ float g_attmean[2][BB][SS][HH];
__device__ float g_attmax[2][BB][SS][HH];
__device__ float g_mpmax[2][BB][SS][PP];
__device__ float g_mpmean[2][BB][SS][PP];
__device__ float g_rowmax[4][BB][PP][SS];
__device__ float g_rowsum[4][BB][PP][SS];

// ---------------- K0: squared weights + lengths -------------------------------
__global__ void k_w2(const float* wf, const float* wm, const float* wa, const float* wx,
                     const int* mp, const int* mh) {
    int bx = blockIdx.x, t = threadIdx.x;
    if (bx < 4) {
        const float* w = (bx == 0) ? wf : (bx == 1) ? wm : (bx == 2) ? wa : wx;
        for (int idx = t; idx < PP * HH; idx += blockDim.x) {
            float v = w[idx];
            (&g_w2[bx][0][0])[idx] = v * v;
        }
    } else {
        int side = bx - 4;
        const int* msk = side ? mh : mp;
        int b = t >> 5, lane = t & 31;
        int s = 0;
#pragma unroll
        for (int k = 0; k < 8; k++) s += msk[b * SS + lane + 32 * k];
        for (int o = 16; o; o >>= 1) s += __shfl_xor_sync(0xffffffffu, s, o);
        if (lane == 0) g_len[side][b] = (float)s;
    }
}

// ---------------- K1a: mask + transpose + plain norms -------------------------
__global__ void k_prep1(const float* cp, const int* mp, const float* ch, const int* mh) {
    int side = blockIdx.y, r = blockIdx.x, b = r / SS, i = r % SS;
    const float* ctx = side ? ch : cp;
    const int* msk = side ? mh : mp;
    int t = threadIdx.x;
    float m = msk[r] ? 1.f : 0.f;
    float x = 0.f;
    if (t < HH) {
        x = ctx[r * HH + t] * m;
        g_c[side][b][i][t] = x;
        g_cT[side][b][t][i] = x;
    }
    float s = x * x;
    __shared__ float sw[4];
    for (int o = 16; o; o >>= 1) s += __shfl_xor_sync(0xffffffffu, s, o);
    if ((t & 31) == 0) sw[t >> 5] = s;
    __syncthreads();
    if (t == 0) g_norm[side][b][i] = sqrtf(sw[0] + sw[1] + sw[2] + sw[3]);
}

// ---------------- K1b: weighted norms (tiled smem matmul) ---------------------
__global__ void __launch_bounds__(128) k_prep2() {
    int gq = blockIdx.x, b = blockIdx.y, side = blockIdx.z;
    int i0 = gq * 16, t = threadIdx.x;
    __shared__ float sW[80][101];
    __shared__ float sX[16][101];
    const float* w2f = &g_w2[0][0][0];
    for (int idx = t; idx < 80 * HH; idx += 128) {
        int pr = idx / HH, h = idx % HH;
        sW[pr][h] = w2f[idx];
    }
    for (int idx = t; idx < 16 * HH; idx += 128) {
        int r = idx / HH, h = idx % HH;
        float x = g_c[side][b][i0 + r][h];
        sX[r][h] = x * x;
    }
    __syncthreads();
    for (int o = t; o < 1280; o += 128) {
        int pr = o % 80, r = o / 80;
        float s = 0.f;
#pragma unroll 4
        for (int h = 0; h < HH; h++) s += sW[pr][h] * sX[r][h];
        g_npw[side][b][i0 + r][pr] = sqrtf(s);
    }
}

// ---------------- K2: gather last valid token ---------------------------------
__global__ void k_last() {
    int side = blockIdx.y, b = blockIdx.x, t = threadIdx.x;
    int len = (int)g_len[side][b];
    int idx = (len > 0) ? (len - 1) : 0;
    if (t < HH) g_last[side][b][t] = g_c[side][b][idx][t];
    if (t < PP) g_nlastw[side][b][t] = g_npw[side][b][idx][t];
    if (t == 127) g_nlast[side][b] = g_norm[side][b][idx];
}

// ---------------- K3: pairwise cosine GEMM (f32x2, 64x16, dup-B) --------------
__global__ void __launch_bounds__(128) k_cos() {
    int b = blockIdx.x, i0 = blockIdx.y * 64, j0 = blockIdx.z * 16;
    int t = threadIdx.x, tx = t & 7, ty = t >> 3;
    __shared__ ull sA[HH][34];
    __shared__ ull sBd[HH][18];
    __shared__ float sni[64], snj[16];
    for (int idx = t; idx < HH * 32; idx += 128) {
        int h = idx >> 5, ip = idx & 31;
        float2 v = *(const float2*)&g_cT[0][b][h][i0 + 2 * ip];
        sA[h][ip] = pk2(v.x, v.y);
    }
    for (int idx = t; idx < HH * 16; idx += 128) {
        int h = idx >> 4, j = idx & 15;
        float v = g_cT[1][b][h][j0 + j];
        sBd[h][j] = pk2(v, v);
    }
    if (t < 64) sni[t] = 1.f / fmaxf(g_norm[0][b][i0 + t], EPSF);
    if (t < 16) snj[t] = 1.f / fmaxf(g_norm[1][b][j0 + t], EPSF);
    __syncthreads();
    ull acc[2][2] = {0, 0, 0, 0};
#pragma unroll 4
    for (int h = 0; h < HH; h++) {
        ulonglong2 a = *(const ulonglong2*)&sA[h][ty * 2];
        ulonglong2 bd = *(const ulonglong2*)&sBd[h][tx * 2];
        acc[0][0] = fma2_(a.x, bd.x, acc[0][0]);
        acc[0][1] = fma2_(a.y, bd.x, acc[0][1]);
        acc[1][0] = fma2_(a.x, bd.y, acc[1][0]);
        acc[1][1] = fma2_(a.y, bd.y, acc[1][1]);
    }
#pragma unroll
    for (int jj = 0; jj < 2; jj++) {
        int j = j0 + tx * 2 + jj;
        float fj = snj[tx * 2 + jj];
#pragma unroll
        for (int rp = 0; rp < 2; rp++) {
            float dl, dh; unpk2(acc[jj][rp], dl, dh);
            int i = i0 + ty * 4 + rp * 2;
            float v0 = dl * sni[ty * 4 + rp * 2] * fj;
            float v1 = dh * sni[ty * 4 + rp * 2 + 1] * fj;
            g_cos[b][i][j] = v0;     g_cosT[b][j][i] = v0;
            g_cos[b][i + 1][j] = v1; g_cosT[b][j][i + 1] = v1;
        }
    }
}

// ---------------- K4: row reductions of cos (warp per row) --------------------
__global__ void __launch_bounds__(128) k_rowred(const int* mp, const int* mh) {
    int side = blockIdx.z, b = blockIdx.y;
    int t = threadIdx.x, w = t >> 5, lane = t & 31;
    int r = blockIdx.x * 4 + w;
    const float* row = side ? &g_cosT[b][r][0] : &g_cos[b][r][0];
    const int* omsk = side ? mp : mh;
    float vmax = -NEGF, vsum = 0.f;
#pragma unroll
    for (int k = 0; k < 8; k++) {
        int j = lane + 32 * k;
        float v = row[j];
        vsum += v;
        vmax = fmaxf(vmax, omsk[b * SS + j] ? v : -NEGF);
    }
    for (int o = 16; o; o >>= 1) {
        vmax = fmaxf(vmax, __shfl_xor_sync(0xffffffffu, vmax, o));
        vsum += __shfl_xor_sync(0xffffffffu, vsum, o);
    }
    if (lane == 0) {
        g_cmax[side][b][r] = vmax;
        g_csum[side][b][r] = vsum;
        g_cmean[side][b][r] = vsum / fmaxf(g_len[1 - side][b], EPSF);
    }
}

// ---------------- K5: attentive mean + max (8 rows/block, 512 blocks) ---------
__global__ void __launch_bounds__(128) k_att(const int* mp, const int* mh) {
    int gq = blockIdx.x, b = blockIdx.y, side = blockIdx.z;
    int i0 = gq * 8, t = threadIdx.x;
    __shared__ float satt[SS][12];
    __shared__ float sbias[SS];
    const int* omsk = side ? mp : mh;
    for (int idx = t; idx < 8 * SS; idx += 128) {
        int r = idx & 7, j = idx >> 3;
        satt[j][r] = side ? g_cosT[b][i0 + r][j] : g_cos[b][i0 + r][j];
    }
    for (int j = t; j < SS; j += 128)
        sbias[j] = omsk[b * SS + j] ? 0.f : -NEGF;
    __syncthreads();
    if (t < HH) {
        const float* oc = &g_c[1 - side][b][0][0];
        float mean[8], vmax[8];
#pragma unroll
        for (int r = 0; r < 8; r++) { mean[r] = 0.f; vmax[r] = -NEGF; }
#pragma unroll 2
        for (int j = 0; j < SS; j++) {
            float v = oc[j * HH + t];
            float bj = sbias[j];
            float4 a0 = *(const float4*)&satt[j][0];
            float4 a1 = *(const float4*)&satt[j][4];
            float a[8] = {a0.x, a0.y, a0.z, a0.w, a1.x, a1.y, a1.z, a1.w};
#pragma unroll
            for (int r = 0; r < 8; r++) {
                mean[r] = fmaf(a[r], v, mean[r]);
                vmax[r] = fmaxf(vmax[r], fmaf(a[r], v, bj));
            }
        }
#pragma unroll
        for (int r = 0; r < 8; r++) {
            int i = i0 + r;
            float denom = fmaxf(g_csum[side][b][i], EPSF);
            g_attmean[side][b][i][t] = mean[r] / denom;
            g_attmax[side][b][i][t] = vmax[r];
        }
    }
}

// ---------------- K6: maxpool GEMM v4 (natural A+B, reg-dup, 8i x 8j) ---------
// grid (PP, BB, 4): z = jbl; block 256 = tx8 x ty32; tile 256i x 64j
// per h per thread: 4 LDS.128 (64B) + 8 MOV + 32 FFMA2 = 64 MACs -> 1 B/MAC
__global__ void __launch_bounds__(256, 2) k_maxpool(const int* mp, const int* mh) {
    int p = blockIdx.x, b = blockIdx.y, jbl = blockIdx.z;
    int j0 = jbl * 64;
    int t = threadIdx.x, tx = t & 7, ty = t >> 3;   // ty 0..31
    __shared__ __align__(16) ull sAp[25][130];      // 128 natural premult i-pairs
    __shared__ __align__(16) ull sBp[25][34];       // 32 natural j-pairs
    __shared__ float siJ[64], sbJ[64];
    __shared__ float sW2[HH];
    // reduction buffers alias sAp (used only after all compute; re-synced)
    float (*sRedM)[65] = (float(*)[65]) & sAp[0][0];
    float (*sRedS)[65] = ((float(*)[65]) & sAp[0][0]) + 32;

    if (t < HH) sW2[t] = g_w2[1][p][t];
    if (t < 64) {
        int j = j0 + t;
        float n = g_npw[1][b][j][PP + p];
        int mj = mh[b * SS + j];
        siJ[t] = (mj && n > 0.f) ? 1.f / n : 0.f;
        sbJ[t] = mj ? 0.f : -NEGF;
    }
    __syncthreads();

    ull acc[8][4];
#pragma unroll
    for (int ia = 0; ia < 8; ia++)
#pragma unroll
        for (int pp = 0; pp < 4; pp++) acc[ia][pp] = 0;

    for (int hc = 0; hc < 4; hc++) {
        int hb = hc * 25;
        __syncthreads();
        for (int idx = t; idx < 25 * 128; idx += 256) {
            int hh = idx >> 7, ip = idx & 127;
            float2 v = *(const float2*)&g_cT[0][b][hb + hh][2 * ip];
            float w = sW2[hb + hh];
            sAp[hh][ip] = pk2(v.x * w, v.y * w);
        }
        for (int idx = t; idx < 25 * 32; idx += 256) {
            int hh = idx >> 5, jp = idx & 31;
            float2 v = *(const float2*)&g_cT[1][b][hb + hh][j0 + 2 * jp];
            sBp[hh][jp] = pk2(v.x, v.y);
        }
        __syncthreads();
#pragma unroll 5
        for (int hh = 0; hh < 25; hh++) {
            ulonglong2 A0 = *(const ulonglong2*)&sAp[hh][ty * 4];
            ulonglong2 A1 = *(const ulonglong2*)&sAp[hh][ty * 4 + 2];
            ulonglong2 B0 = *(const ulonglong2*)&sBp[hh][tx * 4];
            ulonglong2 B1 = *(const ulonglong2*)&sBp[hh][tx * 4 + 2];
            float a0, a1, a2, a3, a4, a5, a6, a7;
            unpk2(A0.x, a0, a1); unpk2(A0.y, a2, a3);
            unpk2(A1.x, a4, a5); unpk2(A1.y, a6, a7);
            ull ad0 = pk2(a0, a0), ad1 = pk2(a1, a1), ad2 = pk2(a2, a2), ad3 = pk2(a3, a3);
            ull ad4 = pk2(a4, a4), ad5 = pk2(a5, a5), ad6 = pk2(a6, a6), ad7 = pk2(a7, a7);
            ull b0 = B0.x, b1 = B0.y, b2 = B1.x, b3 = B1.y;
            acc[0][0] = fma2_(ad0, b0, acc[0][0]); acc[0][1] = fma2_(ad0, b1, acc[0][1]);
            acc[0][2] = fma2_(ad0, b2, acc[0][2]); acc[0][3] = fma2_(ad0, b3, acc[0][3]);
            acc[1][0] = fma2_(ad1, b0, acc[1][0]); acc[1][1] = fma2_(ad1, b1, acc[1][1]);
            acc[1][2] = fma2_(ad1, b2, acc[1][2]); acc[1][3] = fma2_(ad1, b3, acc[1][3]);
            acc[2][0] = fma2_(ad2, b0, acc[2][0]); acc[2][1] = fma2_(ad2, b1, acc[2][1]);
            acc[2][2] = fma2_(ad2, b2, acc[2][2]); acc[2][3] = fma2_(ad2, b3, acc[2][3]);
            acc[3][0] = fma2_(ad3, b0, acc[3][0]); acc[3][1] = fma2_(ad3, b1, acc[3][1]);
            acc[3][2] = fma2_(ad3, b2, acc[3][2]); acc[3][3] = fma2_(ad3, b3, acc[3][3]);
            acc[4][0] = fma2_(ad4, b0, acc[4][0]); acc[4][1] = fma2_(ad4, b1, acc[4][1]);
            acc[4][2] = fma2_(ad4, b2, acc[4][2]); acc[4][3] = fma2_(ad4, b3, acc[4][3]);
            acc[5][0] = fma2_(ad5, b0, acc[5][0]); acc[5][1] = fma2_(ad5, b1, acc[5][1]);
            acc[5][2] = fma2_(ad5, b2, acc[5][2]); acc[5][3] = fma2_(ad5, b3, acc[5][3]);
            acc[6][0] = fma2_(ad6, b0, acc[6][0]); acc[6][1] = fma2_(ad6, b1, acc[6][1]);
            acc[6][2] = fma2_(ad6, b2, acc[6][2]); acc[6][3] = fma2_(ad6, b3, acc[6][3]);
            acc[7][0] = fma2_(ad7, b0, acc[7][0]); acc[7][1] = fma2_(ad7, b1, acc[7][1]);
            acc[7][2] = fma2_(ad7, b2, acc[7][2]); acc[7][3] = fma2_(ad7, b3, acc[7][3]);
        }
    }
    __syncthreads();   // compute done; reduction buffers may overwrite staging

    // epilogue-only per-i constants (keeps mainloop register liveness low)
    float invp[8], biasI[8];
#pragma unroll
    for (int k = 0; k < 8; k++) {
        int i = ty * 8 + k;
        float n = g_npw[0][b][i][PP + p];
        int mi = mp[b * SS + i];
        invp[k] = (mi && n > 0.f) ? 1.f / n : 0.f;
        biasI[k] = mi ? 0.f : -NEGF;
    }
    float len_h = g_len[1][b], len_p = g_len[0][b];

    float pmaxr[8], psumr[8];
#pragma unroll
    for (int k = 0; k < 8; k++) { pmaxr[k] = -NEGF; psumr[k] = 0.f; }
#pragma unroll
    for (int pp = 0; pp < 4; pp++) {
        int jl = tx * 8 + 2 * pp;
        float sj0 = siJ[jl], bj0 = sbJ[jl];
        float sj1 = siJ[jl + 1], bj1 = sbJ[jl + 1];
        float cm0 = -NEGF, cs0 = 0.f, cm1 = -NEGF, cs1 = 0.f;
#pragma unroll
        for (int ia = 0; ia < 8; ia++) {
            float dl, dh; unpk2(acc[ia][pp], dl, dh);
            float v0 = dl * sj0; psumr[ia] += v0; pmaxr[ia] = fmaxf(pmaxr[ia], v0 + bj0);
            float v1 = dh * sj1; psumr[ia] += v1; pmaxr[ia] = fmaxf(pmaxr[ia], v1 + bj1);
            float u0 = dl * invp[ia]; cs0 += u0; cm0 = fmaxf(cm0, u0 + biasI[ia]);
            float u1 = dh * invp[ia]; cs1 += u1; cm1 = fmaxf(cm1, u1 + biasI[ia]);
        }
        sRedM[ty][jl] = cm0; sRedS[ty][jl] = cs0;
        sRedM[ty][jl + 1] = cm1; sRedS[ty][jl + 1] = cs1;
    }
    __syncthreads();
    if (t < 64) {   // columns complete in-block (all 256 i covered)
        float m = -NEGF, s = 0.f;
#pragma unroll
        for (int k = 0; k < 32; k++) { m = fmaxf(m, sRedM[k][t]); s += sRedS[k][t]; }
        int j = j0 + t;
        float inv = siJ[t];
        g_mpmax[1][b][j][p] = m * inv;
        g_mpmean[1][b][j][p] = s * inv / fmaxf(len_p, EPSF);
    }
#pragma unroll
    for (int k = 0; k < 8; k++) {
        float m = pmaxr[k], s = psumr[k];
        for (int o = 4; o; o >>= 1) {
            m = fmaxf(m, __shfl_xor_sync(0xffffffffu, m, o));
            s += __shfl_xor_sync(0xffffffffu, s, o);
        }
        if (tx == 0) {
            int i = ty * 8 + k;
            g_rowmax[jbl][b][p][i] = m;
            g_rowsum[jbl][b][p][i] = s;
        }
    }
    (void)len_h;
}

// ---------------- K6b: combine row partials (4 jbl) ---------------------------
__global__ void k_mpc(const int* mp) {
    int p = blockIdx.x, b = blockIdx.y, t = threadIdx.x;  // 256 threads = i
    float m = g_rowmax[0][b][p][t], s = g_rowsum[0][b][p][t];
#pragma unroll
    for (int k = 1; k < 4; k++) {
        m = fmaxf(m, g_rowmax[k][b][p][t]);
        s += g_rowsum[k][b][p][t];
    }
    float n = g_npw[0][b][t][PP + p];
    int mi = mp[b * SS + t];
    float inv = (mi && n > 0.f) ? 1.f / n : 0.f;
    g_mpmax[0][b][t][p] = m * inv;
    g_mpmean[0][b][t][p] = s * inv / fmaxf(g_len[1][b], EPSF);
}

// ---------------- K7: assemble 105 outputs (8 rows/block) ---------------------
__global__ void __launch_bounds__(128) k_final(float* out) {
    int side = blockIdx.z, b = blockIdx.y, i0 = blockIdx.x * 8, t = threadIdx.x;
    __shared__ float sW[60][101];
    __shared__ float sx[8][HH], sva[8][HH], svm[8][HH], sL[HH];
    __shared__ float sred[8][105];
    const float* w0 = &g_w2[0][0][0];
    const float* w2 = &g_w2[2][0][0];
    const float* w3 = &g_w2[3][0][0];
    for (int idx = t; idx < 20 * HH; idx += 128) {
        int pr = idx / HH, h = idx % HH;
        sW[pr][h] = w0[idx];
        sW[20 + pr][h] = w2[idx];
        sW[40 + pr][h] = w3[idx];
    }
    for (int idx = t; idx < 8 * HH; idx += 128) {
        int r = idx / HH, h = idx % HH;
        sx[r][h] = g_c[side][b][i0 + r][h];
        sva[r][h] = g_attmean[side][b][i0 + r][h];
        svm[r][h] = g_attmax[side][b][i0 + r][h];
    }
    if (t < HH) sL[t] = g_last[1 - side][b][t];
    __syncthreads();
    for (int o = t; o < 840; o += 128) {
        int r = o / 105, k = o % 105;
        float s = 0.f;
        if (k == 0)      { for (int h = 0; h < HH; h++) s += sx[r][h] * sL[h]; }
        else if (k == 1) { for (int h = 0; h < HH; h++) s += sx[r][h] * sva[r][h]; }
        else if (k == 2) { for (int h = 0; h < HH; h++) s += sx[r][h] * svm[r][h]; }
        else if (k == 3) { for (int h = 0; h < HH; h++) s += sva[r][h] * sva[r][h]; }
        else if (k == 4) { for (int h = 0; h < HH; h++) s += svm[r][h] * svm[r][h]; }
        else if (k < 25) { int p = k - 5;  for (int h = 0; h < HH; h++) s += sW[p][h] * sx[r][h] * sL[h]; }
        else if (k < 45) { int p = k - 25; for (int h = 0; h < HH; h++) s += sW[20 + p][h] * sx[r][h] * sva[r][h]; }
        else if (k < 65) { int p = k - 45; for (int h = 0; h < HH; h++) s += sW[20 + p][h] * sva[r][h] * sva[r][h]; }
        else if (k < 85) { int p = k - 65; for (int h = 0; h < HH; h++) s += sW[40 + p][h] * sx[r][h] * svm[r][h]; }
        else             { int p = k - 85; for (int h = 0; h < HH; h++) s += sW[40 + p][h] * svm[r][h] * svm[r][h]; }
        sred[r][k] = s;
    }
    __syncthreads();
    for (int o = t; o < 840; o += 128) {
        int r = o / 105, k = o % 105, i = i0 + r;
        float np = g_norm[side][b][i];
        float ov;
        if (k == 0)      ov = g_cmax[side][b][i];
        else if (k == 1) ov = g_cmean[side][b][i];
        else if (k == 2) ov = sred[r][0] / (fmaxf(np, EPSF) * fmaxf(g_nlast[1 - side][b], EPSF));
        else if (k < 23) {
            int p = k - 3;
            ov = sred[r][5 + p] / (fmaxf(g_npw[side][b][i][p], EPSF) * fmaxf(g_nlastw[1 - side][b][p], EPSF));
        }
        else if (k < 43) ov = g_mpmax[side][b][i][k - 23];
        else if (k < 63) ov = g_mpmean[side][b][i][k - 43];
        else if (k == 63) ov = sred[r][1] / (fmaxf(np, EPSF) * fmaxf(sqrtf(sred[r][3]), EPSF));
        else if (k < 84) {
            int p = k - 64;
            ov = sred[r][25 + p] / (fmaxf(g_npw[side][b][i][2 * PP + p], EPSF) * fmaxf(sqrtf(sred[r][45 + p]), EPSF));
        }
        else if (k == 84) ov = sred[r][2] / (fmaxf(np, EPSF) * fmaxf(sqrtf(sred[r][4]), EPSF));
        else {
            int p = k - 85;
            ov = sred[r][65 + p] / (fmaxf(g_npw[side][b][i][3 * PP + p], EPSF) * fmaxf(sqrtf(sred[r][85 + p]), EPSF));
        }
        out[((size_t)(side * BB + b) * SS + i) * 105 + k] = ov;
    }
}

// ---------------- launch ------------------------------------------------------
extern "C" void kernel_launch(void* const* d_in, const int* in_sizes, int n_in,
                              void* d_out, int out_size) {
    const float* ctx_p = (const float*)d_in[0];
    const int*   mp    = (const int*)d_in[1];
    const float* ctx_h = (const float*)d_in[2];
    const int*   mh    = (const int*)d_in[3];
    const float* wf    = (const float*)d_in[4];
    const float* wm    = (const float*)d_in[5];
    const float* wa    = (const float*)d_in[6];
    const float* wx    = (const float*)d_in[7];
    float* out = (float*)d_out;

    k_w2<<<6, 256>>>(wf, wm, wa, wx, mp, mh);
    k_prep1<<<dim3(BB * SS, 2), 128>>>(ctx_p, mp, ctx_h, mh);
    k_prep2<<<dim3(16, BB, 2), 128>>>();
    k_maxpool<<<dim3(PP, BB, 4), 256>>>(mp, mh);
    k_cos<<<dim3(BB, 4, 16), 128>>>();
    k_rowred<<<dim3(64, BB, 2), 128>>>(mp, mh);
    k_att<<<dim3(32, BB, 2), 128>>>(mp, mh);
    k_last<<<dim3(BB, 2), 128>>>();
    k_mpc<<<dim3(PP, BB), 256>>>(mp);
    k_final<<<dim3(32, BB, 2), 128>>>(out);
}

// round 14
// speedup vs baseline: 1.3926x; 1.3926x over previous
#include <cuda_runtime.h>
#include <math.h>

#define BB 8
#define SS 256
#define HH 100
#define PP 20
#define EPSF 1e-8f
#define NEGF 1e30f
typedef unsigned long long ull;

__device__ __forceinline__ ull pk2(float lo, float hi) {
    ull r; asm("mov.b64 %0, {%1,%2};" : "=l"(r) : "f"(lo), "f"(hi)); return r;
}
__device__ __forceinline__ void unpk2(ull v, float& lo, float& hi) {
    asm("mov.b64 {%0,%1}, %2;" : "=f"(lo), "=f"(hi) : "l"(v));
}
__device__ __forceinline__ ull fma2_(ull a, ull b, ull c) {
    ull d; asm("fma.rn.f32x2 %0, %1, %2, %3;" : "=l"(d) : "l"(a), "l"(b), "l"(c)); return d;
}

// ---------------- scratch -----------------------------------------------------
__device__ float g_c[2][BB][SS][HH];
__device__ float g_cT[2][BB][HH][SS];
__device__ float g_norm[2][BB][SS];
__device__ float g_npw[2][BB][SS][4 * PP];
__device__ float g_w2[4][PP][HH];
__device__ float g_last[2][BB][HH];
__device__ float g_nlast[2][BB];
__device__ float g_nlastw[2][BB][PP];
__device__ float g_len[2][BB];
__device__ float g_cos[BB][SS][SS];
__device__ float g_cosT[BB][SS][SS];
__device__ float g_cmax[2][BB][SS];
__device__ float g_cmean[2][BB][SS];
__device__ float g_csum[2][BB][SS];
__device__ float g_attmean[2][BB][SS][HH];
__device__ float g_attmax[2][BB][SS][HH];
__device__ float g_mpmax[2][BB][SS][PP];
__device__ float g_mpmean[2][BB][SS][PP];
__device__ float g_colmax[2][BB][PP][SS];
__device__ float g_colsum[2][BB][PP][SS];
__device__ float g_rowmax[4][BB][PP][SS];
__device__ float g_rowsum[4][BB][PP][SS];

// ---------------- K0: squared weights + lengths -------------------------------
__global__ void k_w2(const float* wf, const float* wm, const float* wa, const float* wx,
                     const int* mp, const int* mh) {
    int bx = blockIdx.x, t = threadIdx.x;
    if (bx < 4) {
        const float* w = (bx == 0) ? wf : (bx == 1) ? wm : (bx == 2) ? wa : wx;
        for (int idx = t; idx < PP * HH; idx += blockDim.x) {
            float v = w[idx];
            (&g_w2[bx][0][0])[idx] = v * v;
        }
    } else {
        int side = bx - 4;
        const int* msk = side ? mh : mp;
        int b = t >> 5, lane = t & 31;
        int s = 0;
#pragma unroll
        for (int k = 0; k < 8; k++) s += msk[b * SS + lane + 32 * k];
        for (int o = 16; o; o >>= 1) s += __shfl_xor_sync(0xffffffffu, s, o);
        if (lane == 0) g_len[side][b] = (float)s;
    }
}

// ---------------- K1a: mask + transpose + plain norms -------------------------
__global__ void k_prep1(const float* cp, const int* mp, const float* ch, const int* mh) {
    int side = blockIdx.y, r = blockIdx.x, b = r / SS, i = r % SS;
    const float* ctx = side ? ch : cp;
    const int* msk = side ? mh : mp;
    int t = threadIdx.x;
    float m = msk[r] ? 1.f : 0.f;
    float x = 0.f;
    if (t < HH) {
        x = ctx[r * HH + t] * m;
        g_c[side][b][i][t] = x;
        g_cT[side][b][t][i] = x;
    }
    float s = x * x;
    __shared__ float sw[4];
    for (int o = 16; o; o >>= 1) s += __shfl_xor_sync(0xffffffffu, s, o);
    if ((t & 31) == 0) sw[t >> 5] = s;
    __syncthreads();
    if (t == 0) g_norm[side][b][i] = sqrtf(sw[0] + sw[1] + sw[2] + sw[3]);
}

// ---------------- role: prep2 (weighted norms, 128 thr) -----------------------
__device__ __forceinline__ void role_prep2(int gq, int b, int side, char* sm) {
    int i0 = gq * 16, t = threadIdx.x;
    float (*sW)[101] = (float(*)[101])sm;             // 80 x 101
    float (*sX)[101] = (float(*)[101])(sm + 32320);   // 16 x 101
    const float* w2f = &g_w2[0][0][0];
    for (int idx = t; idx < 80 * HH; idx += 128) {
        int pr = idx / HH, h = idx % HH;
        sW[pr][h] = w2f[idx];
    }
    for (int idx = t; idx < 16 * HH; idx += 128) {
        int r = idx / HH, h = idx % HH;
        float x = g_c[side][b][i0 + r][h];
        sX[r][h] = x * x;
    }
    __syncthreads();
    for (int o = t; o < 1280; o += 128) {
        int pr = o % 80, r = o / 80;
        float s = 0.f;
#pragma unroll 4
        for (int h = 0; h < HH; h++) s += sW[pr][h] * sX[r][h];
        g_npw[side][b][i0 + r][pr] = sqrtf(s);
    }
}

// ---------------- role: cos (pairwise cosine GEMM, 128 thr) -------------------
__device__ __forceinline__ void role_cos(int b, int ib, int jb, char* sm) {
    int i0 = ib * 64, j0 = jb * 16;
    int t = threadIdx.x, tx = t & 7, ty = t >> 3;
    ull (*sA)[34] = (ull(*)[34])sm;                   // 100 x 34
    ull (*sBd)[18] = (ull(*)[18])(sm + 27200);        // 100 x 18
    float* sni = (float*)(sm + 41600);                // 64
    float* snj = (float*)(sm + 41856);                // 16
    for (int idx = t; idx < HH * 32; idx += 128) {
        int h = idx >> 5, ip = idx & 31;
        float2 v = *(const float2*)&g_cT[0][b][h][i0 + 2 * ip];
        sA[h][ip] = pk2(v.x, v.y);
    }
    for (int idx = t; idx < HH * 16; idx += 128) {
        int h = idx >> 4, j = idx & 15;
        float v = g_cT[1][b][h][j0 + j];
        sBd[h][j] = pk2(v, v);
    }
    if (t < 64) sni[t] = 1.f / fmaxf(g_norm[0][b][i0 + t], EPSF);
    if (t < 16) snj[t] = 1.f / fmaxf(g_norm[1][b][j0 + t], EPSF);
    __syncthreads();
    ull acc[2][2] = {0, 0, 0, 0};
#pragma unroll 4
    for (int h = 0; h < HH; h++) {
        ulonglong2 a = *(const ulonglong2*)&sA[h][ty * 2];
        ulonglong2 bd = *(const ulonglong2*)&sBd[h][tx * 2];
        acc[0][0] = fma2_(a.x, bd.x, acc[0][0]);
        acc[0][1] = fma2_(a.y, bd.x, acc[0][1]);
        acc[1][0] = fma2_(a.x, bd.y, acc[1][0]);
        acc[1][1] = fma2_(a.y, bd.y, acc[1][1]);
    }
#pragma unroll
    for (int jj = 0; jj < 2; jj++) {
        int j = j0 + tx * 2 + jj;
        float fj = snj[tx * 2 + jj];
#pragma unroll
        for (int rp = 0; rp < 2; rp++) {
            float dl, dh; unpk2(acc[jj][rp], dl, dh);
            int i = i0 + ty * 4 + rp * 2;
            float v0 = dl * sni[ty * 4 + rp * 2] * fj;
            float v1 = dh * sni[ty * 4 + rp * 2 + 1] * fj;
            g_cos[b][i][j] = v0;     g_cosT[b][j][i] = v0;
            g_cos[b][i + 1][j] = v1; g_cosT[b][j][i + 1] = v1;
        }
    }
}

// ---------------- K3: fused cos + prep2 (128 thr) -----------------------------
__global__ void __launch_bounds__(128) k_cos_prep2() {
    __shared__ __align__(16) char sm[41920];
    int bx = blockIdx.x;
    if (bx < 512) {
        role_cos(bx >> 6, (bx >> 4) & 3, bx & 15, sm);
    } else {
        int m = bx - 512;
        role_prep2(m & 15, (m >> 4) & 7, m >> 7, sm);
    }
}

// ---------------- K4: row reductions of cos (warp per row) --------------------
__global__ void __launch_bounds__(128) k_rowred(const int* mp, const int* mh) {
    int side = blockIdx.z, b = blockIdx.y;
    int t = threadIdx.x, w = t >> 5, lane = t & 31;
    int r = blockIdx.x * 4 + w;
    const float* row = side ? &g_cosT[b][r][0] : &g_cos[b][r][0];
    const int* omsk = side ? mp : mh;
    float vmax = -NEGF, vsum = 0.f;
#pragma unroll
    for (int k = 0; k < 8; k++) {
        int j = lane + 32 * k;
        float v = row[j];
        vsum += v;
        vmax = fmaxf(vmax, omsk[b * SS + j] ? v : -NEGF);
    }
    for (int o = 16; o; o >>= 1) {
        vmax = fmaxf(vmax, __shfl_xor_sync(0xffffffffu, vmax, o));
        vsum += __shfl_xor_sync(0xffffffffu, vsum, o);
    }
    if (lane == 0) {
        g_cmax[side][b][r] = vmax;
        g_csum[side][b][r] = vsum;
        g_cmean[side][b][r] = vsum / fmaxf(g_len[1 - side][b], EPSF);
    }
}

// ---------------- role: att (mean+max, 256 thr port) --------------------------
__device__ __forceinline__ void role_att(int gq, int b, int side,
                                         const int* mp, const int* mh, char* sm) {
    int i0 = gq * 8, t = threadIdx.x;
    float (*satt)[12] = (float(*)[12])sm;             // 256 x 12
    float* sbias = (float*)(sm + 12288);              // 256
    const int* omsk = side ? mp : mh;
    for (int idx = t; idx < 8 * SS; idx += 256) {
        int r = idx & 7, j = idx >> 3;
        satt[j][r] = side ? g_cosT[b][i0 + r][j] : g_cos[b][i0 + r][j];
    }
    for (int j = t; j < SS; j += 256)
        sbias[j] = omsk[b * SS + j] ? 0.f : -NEGF;
    __syncthreads();
    if (t < HH) {
        const float* oc = &g_c[1 - side][b][0][0];
        float mean[8], vmax[8];
#pragma unroll
        for (int r = 0; r < 8; r++) { mean[r] = 0.f; vmax[r] = -NEGF; }
#pragma unroll 2
        for (int j = 0; j < SS; j++) {
            float v = oc[j * HH + t];
            float bj = sbias[j];
            float4 a0 = *(const float4*)&satt[j][0];
            float4 a1 = *(const float4*)&satt[j][4];
            float a[8] = {a0.x, a0.y, a0.z, a0.w, a1.x, a1.y, a1.z, a1.w};
#pragma unroll
            for (int r = 0; r < 8; r++) {
                mean[r] = fmaf(a[r], v, mean[r]);
                vmax[r] = fmaxf(vmax[r], fmaf(a[r], v, bj));
            }
        }
#pragma unroll
        for (int r = 0; r < 8; r++) {
            int i = i0 + r;
            float denom = fmaxf(g_csum[side][b][i], EPSF);
            g_attmean[side][b][i][t] = mean[r] / denom;
            g_attmax[side][b][i][t] = vmax[r];
        }
    }
}

// ---------------- role: maxpool v3b (256 thr, exact R11 code) -----------------
__device__ __forceinline__ void role_mp(int p, int b, int z,
                                        const int* mp, const int* mh, char* sm) {
    int ibl = z >> 2, jbl = z & 3;
    int i0 = ibl * 128, j0 = jbl * 64;
    int t = threadIdx.x, tx = t & 7, ty = t >> 3;
    ull (*sAd)[132] = (ull(*)[132])sm;                // 25 x 132
    ull (*sBp)[36] = (ull(*)[36])(sm + 26400);        // 25 x 36
    float* siJ = (float*)(sm + 33600);                // 64
    float* sbJ = (float*)(sm + 33856);                // 64
    float* sW2 = (float*)(sm + 34112);                // 100
    float (*sRedM)[65] = (float(*)[65])sm;            // alias staging
    float (*sRedS)[65] = ((float(*)[65])sm) + 32;

    if (t < HH) sW2[t] = g_w2[1][p][t];
    if (t < 64) {
        int j = j0 + t;
        float n = g_npw[1][b][j][PP + p];
        int mj = mh[b * SS + j];
        siJ[t] = (mj && n > 0.f) ? 1.f / n : 0.f;
        sbJ[t] = mj ? 0.f : -NEGF;
    }
    float invp[4], biasI[4];
#pragma unroll
    for (int r = 0; r < 4; r++) {
        int i = i0 + ty * 4 + r;
        float n = g_npw[0][b][i][PP + p];
        int mi = mp[b * SS + i];
        invp[r] = (mi && n > 0.f) ? 1.f / n : 0.f;
        biasI[r] = mi ? 0.f : -NEGF;
    }
    __syncthreads();

    ull acc[4][4];
#pragma unroll
    for (int ia = 0; ia < 4; ia++)
#pragma unroll
        for (int pp = 0; pp < 4; pp++) acc[ia][pp] = 0;

    for (int hc = 0; hc < 4; hc++) {
        int hb = hc * 25;
        __syncthreads();
        for (int idx = t; idx < 25 * 128; idx += 256) {
            int hh = idx >> 7, il = idx & 127;
            float v = g_cT[0][b][hb + hh][i0 + il] * sW2[hb + hh];
            sAd[hh][il] = pk2(v, v);
        }
        for (int idx = t; idx < 25 * 32; idx += 256) {
            int hh = idx >> 5, jp = idx & 31;
            float2 v = *(const float2*)&g_cT[1][b][hb + hh][j0 + 2 * jp];
            sBp[hh][jp] = pk2(v.x, v.y);
        }
        __syncthreads();
#pragma unroll 5
        for (int hh = 0; hh < 25; hh++) {
            ulonglong2 a0 = *(const ulonglong2*)&sAd[hh][ty * 4];
            ulonglong2 a1 = *(const ulonglong2*)&sAd[hh][ty * 4 + 2];
            ulonglong2 b0 = *(const ulonglong2*)&sBp[hh][tx * 4];
            ulonglong2 b1 = *(const ulonglong2*)&sBp[hh][tx * 4 + 2];
            acc[0][0] = fma2_(a0.x, b0.x, acc[0][0]);
            acc[0][1] = fma2_(a0.x, b0.y, acc[0][1]);
            acc[0][2] = fma2_(a0.x, b1.x, acc[0][2]);
            acc[0][3] = fma2_(a0.x, b1.y, acc[0][3]);
            acc[1][0] = fma2_(a0.y, b0.x, acc[1][0]);
            acc[1][1] = fma2_(a0.y, b0.y, acc[1][1]);
            acc[1][2] = fma2_(a0.y, b1.x, acc[1][2]);
            acc[1][3] = fma2_(a0.y, b1.y, acc[1][3]);
            acc[2][0] = fma2_(a1.x, b0.x, acc[2][0]);
            acc[2][1] = fma2_(a1.x, b0.y, acc[2][1]);
            acc[2][2] = fma2_(a1.x, b1.x, acc[2][2]);
            acc[2][3] = fma2_(a1.x, b1.y, acc[2][3]);
            acc[3][0] = fma2_(a1.y, b0.x, acc[3][0]);
            acc[3][1] = fma2_(a1.y, b0.y, acc[3][1]);
            acc[3][2] = fma2_(a1.y, b1.x, acc[3][2]);
            acc[3][3] = fma2_(a1.y, b1.y, acc[3][3]);
        }
    }
    __syncthreads();   // compute done before reductions overwrite staging

    float pmaxr[4], psumr[4];
#pragma unroll
    for (int r = 0; r < 4; r++) { pmaxr[r] = -NEGF; psumr[r] = 0.f; }
#pragma unroll
    for (int pp = 0; pp < 4; pp++) {
        int jl = tx * 8 + 2 * pp;
        float sj0 = siJ[jl], bj0 = sbJ[jl];
        float sj1 = siJ[jl + 1], bj1 = sbJ[jl + 1];
        float cm0 = -NEGF, cs0 = 0.f, cm1 = -NEGF, cs1 = 0.f;
#pragma unroll
        for (int ia = 0; ia < 4; ia++) {
            float dl, dh; unpk2(acc[ia][pp], dl, dh);
            float v0 = dl * sj0; psumr[ia] += v0; pmaxr[ia] = fmaxf(pmaxr[ia], v0 + bj0);
            float v1 = dh * sj1; psumr[ia] += v1; pmaxr[ia] = fmaxf(pmaxr[ia], v1 + bj1);
            float u0 = dl * invp[ia]; cs0 += u0; cm0 = fmaxf(cm0, u0 + biasI[ia]);
            float u1 = dh * invp[ia]; cs1 += u1; cm1 = fmaxf(cm1, u1 + biasI[ia]);
        }
        sRedM[ty][jl] = cm0; sRedS[ty][jl] = cs0;
        sRedM[ty][jl + 1] = cm1; sRedS[ty][jl + 1] = cs1;
    }
    __syncthreads();
    if (t < 64) {
        float m = -NEGF, s = 0.f;
#pragma unroll
        for (int k = 0; k < 32; k++) { m = fmaxf(m, sRedM[k][t]); s += sRedS[k][t]; }
        g_colmax[ibl][b][p][j0 + t] = m;
        g_colsum[ibl][b][p][j0 + t] = s;
    }
#pragma unroll
    for (int r = 0; r < 4; r++) {
        float m = pmaxr[r], s = psumr[r];
        for (int o = 4; o; o >>= 1) {
            m = fmaxf(m, __shfl_xor_sync(0xffffffffu, m, o));
            s += __shfl_xor_sync(0xffffffffu, s, o);
        }
        if (tx == 0) {
            int i = i0 + ty * 4 + r;
            g_rowmax[jbl][b][p][i] = m;
            g_rowsum[jbl][b][p][i] = s;
        }
    }
}

// ---------------- K6: fused maxpool + att (256 thr) ---------------------------
__global__ void __launch_bounds__(256) k_mp_att(const int* mp, const int* mh) {
    __shared__ __align__(16) char sm[34512];
    int bx = blockIdx.x;
    if (bx < 1280) {
        int p = bx / 64, rem = bx & 63;
        role_mp(p, rem >> 3, rem & 7, mp, mh, sm);
    } else {
        int a = bx - 1280;
        role_att(a & 31, (a >> 5) & 7, a >> 8, mp, mh, sm);
    }
}

// ---------------- K2: gather last valid token ---------------------------------
__global__ void k_last() {
    int side = blockIdx.y, b = blockIdx.x, t = threadIdx.x;
    int len = (int)g_len[side][b];
    int idx = (len > 0) ? (len - 1) : 0;
    if (t < HH) g_last[side][b][t] = g_c[side][b][idx][t];
    if (t < PP) g_nlastw[side][b][t] = g_npw[side][b][idx][t];
    if (t == 127) g_nlast[side][b] = g_norm[side][b][idx];
}

// ---------------- K6b: combine partials (both directions) ---------------------
__global__ void k_mpc(const int* mp, const int* mh) {
    int p = blockIdx.x, b = blockIdx.y, t = threadIdx.x;  // 256 threads
    {
        float m = fmaxf(g_colmax[0][b][p][t], g_colmax[1][b][p][t]);
        float s = g_colsum[0][b][p][t] + g_colsum[1][b][p][t];
        float n = g_npw[1][b][t][PP + p];
        int mj = mh[b * SS + t];
        float inv = (mj && n > 0.f) ? 1.f / n : 0.f;
        g_mpmax[1][b][t][p] = m * inv;
        g_mpmean[1][b][t][p] = s * inv / fmaxf(g_len[0][b], EPSF);
    }
    {
        float m = g_rowmax[0][b][p][t], s = g_rowsum[0][b][p][t];
#pragma unroll
        for (int k = 1; k < 4; k++) {
            m = fmaxf(m, g_rowmax[k][b][p][t]);
            s += g_rowsum[k][b][p][t];
        }
        float n = g_npw[0][b][t][PP + p];
        int mi = mp[b * SS + t];
        float inv = (mi && n > 0.f) ? 1.f / n : 0.f;
        g_mpmax[0][b][t][p] = m * inv;
        g_mpmean[0][b][t][p] = s * inv / fmaxf(g_len[1][b], EPSF);
    }
}

// ---------------- K7: assemble 105 outputs (8 rows/block) ---------------------
__global__ void __launch_bounds__(128) k_final(float* out) {
    int side = blockIdx.z, b = blockIdx.y, i0 = blockIdx.x * 8, t = threadIdx.x;
    __shared__ float sW[60][101];
    __shared__ float sx[8][HH], sva[8][HH], svm[8][HH], sL[HH];
    __shared__ float sred[8][105];
    const float* w0 = &g_w2[0][0][0];
    const float* w2 = &g_w2[2][0][0];
    const float* w3 = &g_w2[3][0][0];
    for (int idx = t; idx < 20 * HH; idx += 128) {
        int pr = idx / HH, h = idx % HH;
        sW[pr][h] = w0[idx];
        sW[20 + pr][h] = w2[idx];
        sW[40 + pr][h] = w3[idx];
    }
    for (int idx = t; idx < 8 * HH; idx += 128) {
        int r = idx / HH, h = idx % HH;
        sx[r][h] = g_c[side][b][i0 + r][h];
        sva[r][h] = g_attmean[side][b][i0 + r][h];
        svm[r][h] = g_attmax[side][b][i0 + r][h];
    }
    if (t < HH) sL[t] = g_last[1 - side][b][t];
    __syncthreads();
    for (int o = t; o < 840; o += 128) {
        int r = o / 105, k = o % 105;
        float s = 0.f;
        if (k == 0)      { for (int h = 0; h < HH; h++) s += sx[r][h] * sL[h]; }
        else if (k == 1) { for (int h = 0; h < HH; h++) s += sx[r][h] * sva[r][h]; }
        else if (k == 2) { for (int h = 0; h < HH; h++) s += sx[r][h] * svm[r][h]; }
        else if (k == 3) { for (int h = 0; h < HH; h++) s += sva[r][h] * sva[r][h]; }
        else if (k == 4) { for (int h = 0; h < HH; h++) s += svm[r][h] * svm[r][h]; }
        else if (k < 25) { int p = k - 5;  for (int h = 0; h < HH; h++) s += sW[p][h] * sx[r][h] * sL[h]; }
        else if (k < 45) { int p = k - 25; for (int h = 0; h < HH; h++) s += sW[20 + p][h] * sx[r][h] * sva[r][h]; }
        else if (k < 65) { int p = k - 45; for (int h = 0; h < HH; h++) s += sW[20 + p][h] * sva[r][h] * sva[r][h]; }
        else if (k < 85) { int p = k - 65; for (int h = 0; h < HH; h++) s += sW[40 + p][h] * sx[r][h] * svm[r][h]; }
        else             { int p = k - 85; for (int h = 0; h < HH; h++) s += sW[40 + p][h] * svm[r][h] * svm[r][h]; }
        sred[r][k] = s;
    }
    __syncthreads();
    for (int o = t; o < 840; o += 128) {
        int r = o / 105, k = o % 105, i = i0 + r;
        float np = g_norm[side][b][i];
        float ov;
        if (k == 0)      ov = g_cmax[side][b][i];
        else if (k == 1) ov = g_cmean[side][b][i];
        else if (k == 2) ov = sred[r][0] / (fmaxf(np, EPSF) * fmaxf(g_nlast[1 - side][b], EPSF));
        else if (k < 23) {
            int p = k - 3;
            ov = sred[r][5 + p] / (fmaxf(g_npw[side][b][i][p], EPSF) * fmaxf(g_nlastw[1 - side][b][p], EPSF));
        }
        else if (k < 43) ov = g_mpmax[side][b][i][k - 23];
        else if (k < 63) ov = g_mpmean[side][b][i][k - 43];
        else if (k == 63) ov = sred[r][1] / (fmaxf(np, EPSF) * fmaxf(sqrtf(sred[r][3]), EPSF));
        else if (k < 84) {
            int p = k - 64;
            ov = sred[r][25 + p] / (fmaxf(g_npw[side][b][i][2 * PP + p], EPSF) * fmaxf(sqrtf(sred[r][45 + p]), EPSF));
        }
        else if (k == 84) ov = sred[r][2] / (fmaxf(np, EPSF) * fmaxf(sqrtf(sred[r][4]), EPSF));
        else {
            int p = k - 85;
            ov = sred[r][65 + p] / (fmaxf(g_npw[side][b][i][3 * PP + p], EPSF) * fmaxf(sqrtf(sred[r][85 + p]), EPSF));
        }
        out[((size_t)(side * BB + b) * SS + i) * 105 + k] = ov;
    }
}

// ---------------- launch ------------------------------------------------------
extern "C" void kernel_launch(void* const* d_in, const int* in_sizes, int n_in,
                              void* d_out, int out_size) {
    const float* ctx_p = (const float*)d_in[0];
    const int*   mp    = (const int*)d_in[1];
    const float* ctx_h = (const float*)d_in[2];
    const int*   mh    = (const int*)d_in[3];
    const float* wf    = (const float*)d_in[4];
    const float* wm    = (const float*)d_in[5];
    const float* wa    = (const float*)d_in[6];
    const float* wx    = (const float*)d_in[7];
    float* out = (float*)d_out;

    k_w2<<<6, 256>>>(wf, wm, wa, wx, mp, mh);
    k_prep1<<<dim3(BB * SS, 2), 128>>>(ctx_p, mp, ctx_h, mh);
    k_cos_prep2<<<768, 128>>>();
    k_rowred<<<dim3(64, BB, 2), 128>>>(mp, mh);
    k_mp_att<<<1792, 256>>>(mp, mh);
    k_last<<<dim3(BB, 2), 128>>>();
    k_mpc<<<dim3(PP, BB), 256>>>(mp, mh);
    k_final<<<dim3(32, BB, 2), 128>>>(out);
}

// round 17
// speedup vs baseline: 1.5902x; 1.1419x over previous
#include <cuda_runtime.h>
#include <math.h>

#define BB 8
#define SS 256
#define HH 100
#define PP 20
#define EPSF 1e-8f
#define NEGF 1e30f
typedef unsigned long long ull;

__device__ __forceinline__ ull pk2(float lo, float hi) {
    ull r; asm("mov.b64 %0, {%1,%2};" : "=l"(r) : "f"(lo), "f"(hi)); return r;
}
__device__ __forceinline__ void unpk2(ull v, float& lo, float& hi) {
    asm("mov.b64 {%0,%1}, %2;" : "=f"(lo), "=f"(hi) : "l"(v));
}
__device__ __forceinline__ ull fma2_(ull a, ull b, ull c) {
    ull d; asm("fma.rn.f32x2 %0, %1, %2, %3;" : "=l"(d) : "l"(a), "l"(b), "l"(c)); return d;
}

// ---------------- scratch -----------------------------------------------------
__device__ float g_c[2][BB][SS][HH];
__device__ float g_cT[2][BB][HH][SS];
__device__ float g_norm[2][BB][SS];
__device__ float g_npw[2][BB][SS][4 * PP];
__device__ float g_w2[4][PP][HH];
__device__ float g_last[2][BB][HH];
__device__ float g_nlast[2][BB];
__device__ float g_nlastw[2][BB][PP];
__device__ float g_len[2][BB];
__device__ float g_cos[BB][SS][SS];
__device__ float g_cosT[BB][SS][SS];
__device__ float g_cmax[2][BB][SS];
__device__ float g_cmean[2][BB][SS];
__device__ float g_attmean[2][BB][SS][HH];
__device__ float g_attmax[2][BB][SS][HH];
__device__ float g_mpmax1[BB][SS][PP];     // h-side, written in-block
__device__ float g_mpmean1[BB][SS][PP];
__device__ float g_rowmax[8][BB][PP][SS];  // p-side partials per jbl
__device__ float g_rowsum[8][BB][PP][SS];

// ---------------- K0: squared weights + lengths -------------------------------
__global__ void k_w2(const float* wf, const float* wm, const float* wa, const float* wx,
                     const int* mp, const int* mh) {
    int bx = blockIdx.x, t = threadIdx.x;
    if (bx < 4) {
        const float* w = (bx == 0) ? wf : (bx == 1) ? wm : (bx == 2) ? wa : wx;
        for (int idx = t; idx < PP * HH; idx += blockDim.x) {
            float v = w[idx];
            (&g_w2[bx][0][0])[idx] = v * v;
        }
    } else {
        int side = bx - 4;
        const int* msk = side ? mh : mp;
        int b = t >> 5, lane = t & 31;
        int s = 0;
#pragma unroll
        for (int k = 0; k < 8; k++) s += msk[b * SS + lane + 32 * k];
        for (int o = 16; o; o >>= 1) s += __shfl_xor_sync(0xffffffffu, s, o);
        if (lane == 0) g_len[side][b] = (float)s;
    }
}

// ---------------- K1a: mask + transpose + plain norms -------------------------
__global__ void k_prep1(const float* cp, const int* mp, const float* ch, const int* mh) {
    int side = blockIdx.y, r = blockIdx.x, b = r / SS, i = r % SS;
    const float* ctx = side ? ch : cp;
    const int* msk = side ? mh : mp;
    int t = threadIdx.x;
    float m = msk[r] ? 1.f : 0.f;
    float x = 0.f;
    if (t < HH) {
        x = ctx[r * HH + t] * m;
        g_c[side][b][i][t] = x;
        g_cT[side][b][t][i] = x;
    }
    float s = x * x;
    __shared__ float sw[4];
    for (int o = 16; o; o >>= 1) s += __shfl_xor_sync(0xffffffffu, s, o);
    if ((t & 31) == 0) sw[t >> 5] = s;
    __syncthreads();
    if (t == 0) g_norm[side][b][i] = sqrtf(sw[0] + sw[1] + sw[2] + sw[3]);
}

// ---------------- role: prep2 (weighted norms, 128 thr) -----------------------
__device__ __forceinline__ void role_prep2(int gq, int b, int side, char* sm) {
    int i0 = gq * 16, t = threadIdx.x;
    float (*sW)[101] = (float(*)[101])sm;
    float (*sX)[101] = (float(*)[101])(sm + 32320);
    const float* w2f = &g_w2[0][0][0];
    for (int idx = t; idx < 80 * HH; idx += 128) {
        int pr = idx / HH, h = idx % HH;
        sW[pr][h] = w2f[idx];
    }
    for (int idx = t; idx < 16 * HH; idx += 128) {
        int r = idx / HH, h = idx % HH;
        float x = g_c[side][b][i0 + r][h];
        sX[r][h] = x * x;
    }
    __syncthreads();
    for (int o = t; o < 1280; o += 128) {
        int pr = o % 80, r = o / 80;
        float s = 0.f;
#pragma unroll 4
        for (int h = 0; h < HH; h++) s += sW[pr][h] * sX[r][h];
        g_npw[side][b][i0 + r][pr] = sqrtf(s);
    }
}

// ---------------- role: cos (pairwise cosine GEMM, 128 thr) -------------------
__device__ __forceinline__ void role_cos(int b, int ib, int jb, char* sm) {
    int i0 = ib * 64, j0 = jb * 16;
    int t = threadIdx.x, tx = t & 7, ty = t >> 3;
    ull (*sA)[34] = (ull(*)[34])sm;
    ull (*sBd)[18] = (ull(*)[18])(sm + 27200);
    float* sni = (float*)(sm + 41600);
    float* snj = (float*)(sm + 41856);
    for (int idx = t; idx < HH * 32; idx += 128) {
        int h = idx >> 5, ip = idx & 31;
        float2 v = *(const float2*)&g_cT[0][b][h][i0 + 2 * ip];
        sA[h][ip] = pk2(v.x, v.y);
    }
    for (int idx = t; idx < HH * 16; idx += 128) {
        int h = idx >> 4, j = idx & 15;
        float v = g_cT[1][b][h][j0 + j];
        sBd[h][j] = pk2(v, v);
    }
    if (t < 64) sni[t] = 1.f / fmaxf(g_norm[0][b][i0 + t], EPSF);
    if (t < 16) snj[t] = 1.f / fmaxf(g_norm[1][b][j0 + t], EPSF);
    __syncthreads();
    ull acc[2][2] = {0, 0, 0, 0};
#pragma unroll 4
    for (int h = 0; h < HH; h++) {
        ulonglong2 a = *(const ulonglong2*)&sA[h][ty * 2];
        ulonglong2 bd = *(const ulonglong2*)&sBd[h][tx * 2];
        acc[0][0] = fma2_(a.x, bd.x, acc[0][0]);
        acc[0][1] = fma2_(a.y, bd.x, acc[0][1]);
        acc[1][0] = fma2_(a.x, bd.y, acc[1][0]);
        acc[1][1] = fma2_(a.y, bd.y, acc[1][1]);
    }
#pragma unroll
    for (int jj = 0; jj < 2; jj++) {
        int j = j0 + tx * 2 + jj;
        float fj = snj[tx * 2 + jj];
#pragma unroll
        for (int rp = 0; rp < 2; rp++) {
            float dl, dh; unpk2(acc[jj][rp], dl, dh);
            int i = i0 + ty * 4 + rp * 2;
            float v0 = dl * sni[ty * 4 + rp * 2] * fj;
            float v1 = dh * sni[ty * 4 + rp * 2 + 1] * fj;
            g_cos[b][i][j] = v0;     g_cosT[b][j][i] = v0;
            g_cos[b][i + 1][j] = v1; g_cosT[b][j][i + 1] = v1;
        }
    }
}

// ---------------- K3: fused cos + prep2 (128 thr) -----------------------------
__global__ void __launch_bounds__(128) k_cos_prep2() {
    __shared__ __align__(16) char sm[41920];
    int bx = blockIdx.x;
    if (bx < 512) {
        role_cos(bx >> 6, (bx >> 4) & 3, bx & 15, sm);
    } else {
        int m = bx - 512;
        role_prep2(m & 15, (m >> 4) & 7, m >> 7, sm);
    }
}

// ---------------- role: rowred (256 thr, 8 rows/block) ------------------------
__device__ __forceinline__ void role_rr(int rblk, int b, int side,
                                        const int* mp, const int* mh) {
    int t = threadIdx.x, w = t >> 5, lane = t & 31;
    int r = rblk * 8 + w;
    const float* row = side ? &g_cosT[b][r][0] : &g_cos[b][r][0];
    const int* omsk = side ? mp : mh;
    float vmax = -NEGF, vsum = 0.f;
#pragma unroll
    for (int k = 0; k < 8; k++) {
        int j = lane + 32 * k;
        float v = row[j];
        vsum += v;
        vmax = fmaxf(vmax, omsk[b * SS + j] ? v : -NEGF);
    }
    for (int o = 16; o; o >>= 1) {
        vmax = fmaxf(vmax, __shfl_xor_sync(0xffffffffu, vmax, o));
        vsum += __shfl_xor_sync(0xffffffffu, vsum, o);
    }
    if (lane == 0) {
        g_cmax[side][b][r] = vmax;
        g_cmean[side][b][r] = vsum / fmaxf(g_len[1 - side][b], EPSF);
    }
}

// ---------------- role: last gather (no deps beyond prep2) --------------------
__device__ __forceinline__ void role_last(int side) {
    int b = threadIdx.x >> 5;  // unused path guard below uses full t
    (void)b;
    int t = threadIdx.x;
    for (int bb = 0; bb < BB; bb++) {
        int len = (int)g_len[side][bb];
        int idx = (len > 0) ? (len - 1) : 0;
        if (t < HH) g_last[side][bb][t] = g_c[side][bb][idx][t];
        if (t < PP) g_nlastw[side][bb][t] = g_npw[side][bb][idx][t];
        if (t == 127) g_nlast[side][bb] = g_norm[side][bb][idx];
    }
}

// ---------------- role: att (mean+max, 256 thr, self-contained csum) ----------
__device__ __forceinline__ void role_att(int gq, int b, int side,
                                         const int* mp, const int* mh, char* sm) {
    int i0 = gq * 8, t = threadIdx.x;
    float (*satt)[12] = (float(*)[12])sm;             // 256 x 12
    float* sbias = (float*)(sm + 12288);              // 256
    float* rsum = (float*)(sm + 13312);               // 8
    const int* omsk = side ? mp : mh;
    for (int idx = t; idx < 8 * SS; idx += 256) {
        int r = idx & 7, j = idx >> 3;
        satt[j][r] = side ? g_cosT[b][i0 + r][j] : g_cos[b][i0 + r][j];
    }
    for (int j = t; j < SS; j += 256)
        sbias[j] = omsk[b * SS + j] ? 0.f : -NEGF;
    __syncthreads();
    {   // in-role row sums (denominators)
        int w = t >> 5, lane = t & 31;
        float s = 0.f;
#pragma unroll
        for (int k = 0; k < 8; k++) s += satt[lane + 32 * k][w];
        for (int o = 16; o; o >>= 1) s += __shfl_xor_sync(0xffffffffu, s, o);
        if (lane == 0) rsum[w] = s;
    }
    __syncthreads();
    if (t < HH) {
        const float* oc = &g_c[1 - side][b][0][0];
        float mean[8], vmax[8];
#pragma unroll
        for (int r = 0; r < 8; r++) { mean[r] = 0.f; vmax[r] = -NEGF; }
#pragma unroll 2
        for (int j = 0; j < SS; j++) {
            float v = oc[j * HH + t];
            float bj = sbias[j];
            float4 a0 = *(const float4*)&satt[j][0];
            float4 a1 = *(const float4*)&satt[j][4];
            float a[8] = {a0.x, a0.y, a0.z, a0.w, a1.x, a1.y, a1.z, a1.w};
#pragma unroll
            for (int r = 0; r < 8; r++) {
                mean[r] = fmaf(a[r], v, mean[r]);
                vmax[r] = fmaxf(vmax[r], fmaf(a[r], v, bj));
            }
        }
#pragma unroll
        for (int r = 0; r < 8; r++) {
            int i = i0 + r;
            float denom = fmaxf(rsum[r], EPSF);
            g_attmean[side][b][i][t] = mean[r] / denom;
            g_attmax[side][b][i][t] = vmax[r];
        }
    }
}

// ---------------- role: maxpool v5 (256i x 32j, 8i x 4j per thread) -----------
// per h per thread: 3 LDS.128 (48B) + 4 reg-dup + 16 FFMA2 = 32 MACs
__device__ __forceinline__ void role_mp(int p, int b, int jbl,
                                        const int* mp, const int* mh, char* sm) {
    int j0 = jbl * 32;
    int t = threadIdx.x, tx = t & 7, ty = t >> 3;   // ty 0..31 -> 8 i each
    ull (*sAp)[130] = (ull(*)[130])sm;              // 25 x (128 natural premult i-pairs)
    ull (*sBp)[18] = (ull(*)[18])(sm + 26000);      // 25 x (16 natural j-pairs)
    float* siJ = (float*)(sm + 29600);              // 32
    float* sbJ = (float*)(sm + 29728);              // 32
    float* sW2 = (float*)(sm + 29856);              // 100
    float (*sRedM)[33] = (float(*)[33])sm;          // alias staging post-compute
    float (*sRedS)[33] = ((float(*)[33])sm) + 32;

    if (t < HH) sW2[t] = g_w2[1][p][t];
    if (t < 32) {
        int j = j0 + t;
        float n = g_npw[1][b][j][PP + p];
        int mj = mh[b * SS + j];
        siJ[t] = (mj && n > 0.f) ? 1.f / n : 0.f;
        sbJ[t] = mj ? 0.f : -NEGF;
    }
    __syncthreads();

    ull acc[4][4];   // [j-dup][i-pair]
#pragma unroll
    for (int jd = 0; jd < 4; jd++)
#pragma unroll
        for (int ip = 0; ip < 4; ip++) acc[jd][ip] = 0;

    for (int hc = 0; hc < 4; hc++) {
        int hb = hc * 25;
        __syncthreads();
        for (int idx = t; idx < 25 * 128; idx += 256) {
            int hh = idx >> 7, ip = idx & 127;
            float2 v = *(const float2*)&g_cT[0][b][hb + hh][2 * ip];
            float w = sW2[hb + hh];
            sAp[hh][ip] = pk2(v.x * w, v.y * w);
        }
        for (int idx = t; idx < 25 * 16; idx += 256) {
            int hh = idx >> 4, jp = idx & 15;
            float2 v = *(const float2*)&g_cT[1][b][hb + hh][j0 + 2 * jp];
            sBp[hh][jp] = pk2(v.x, v.y);
        }
        __syncthreads();
#pragma unroll 5
        for (int hh = 0; hh < 25; hh++) {
            ulonglong2 A0 = *(const ulonglong2*)&sAp[hh][ty * 4];
            ulonglong2 A1 = *(const ulonglong2*)&sAp[hh][ty * 4 + 2];
            ulonglong2 B0 = *(const ulonglong2*)&sBp[hh][tx * 2];
            float b0, b1, b2, b3;
            unpk2(B0.x, b0, b1); unpk2(B0.y, b2, b3);
            ull bd0 = pk2(b0, b0), bd1 = pk2(b1, b1);
            ull bd2 = pk2(b2, b2), bd3 = pk2(b3, b3);
            acc[0][0] = fma2_(A0.x, bd0, acc[0][0]);
            acc[0][1] = fma2_(A0.y, bd0, acc[0][1]);
            acc[0][2] = fma2_(A1.x, bd0, acc[0][2]);
            acc[0][3] = fma2_(A1.y, bd0, acc[0][3]);
            acc[1][0] = fma2_(A0.x, bd1, acc[1][0]);
            acc[1][1] = fma2_(A0.y, bd1, acc[1][1]);
            acc[1][2] = fma2_(A1.x, bd1, acc[1][2]);
            acc[1][3] = fma2_(A1.y, bd1, acc[1][3]);
            acc[2][0] = fma2_(A0.x, bd2, acc[2][0]);
            acc[2][1] = fma2_(A0.y, bd2, acc[2][1]);
            acc[2][2] = fma2_(A1.x, bd2, acc[2][2]);
            acc[2][3] = fma2_(A1.y, bd2, acc[2][3]);
            acc[3][0] = fma2_(A0.x, bd3, acc[3][0]);
            acc[3][1] = fma2_(A0.y, bd3, acc[3][1]);
            acc[3][2] = fma2_(A1.x, bd3, acc[3][2]);
            acc[3][3] = fma2_(A1.y, bd3, acc[3][3]);
        }
    }
    __syncthreads();   // compute done before reductions overwrite staging

    float invp[8], biasI[8];
#pragma unroll
    for (int k = 0; k < 8; k++) {
        int i = ty * 8 + k;
        float n = g_npw[0][b][i][PP + p];
        int mi = mp[b * SS + i];
        invp[k] = (mi && n > 0.f) ? 1.f / n : 0.f;
        biasI[k] = mi ? 0.f : -NEGF;
    }
    float pmaxr[8], psumr[8];
#pragma unroll
    for (int k = 0; k < 8; k++) { pmaxr[k] = -NEGF; psumr[k] = 0.f; }
#pragma unroll
    for (int jd = 0; jd < 4; jd++) {
        int jl = tx * 4 + jd;
        float sj = siJ[jl], bj = sbJ[jl];
        float cm = -NEGF, cs = 0.f;
#pragma unroll
        for (int ip = 0; ip < 4; ip++) {
            float dl, dh; unpk2(acc[jd][ip], dl, dh);
            int il0 = 2 * ip, il1 = 2 * ip + 1;
            float v0 = dl * sj; psumr[il0] += v0; pmaxr[il0] = fmaxf(pmaxr[il0], v0 + bj);
            float v1 = dh * sj; psumr[il1] += v1; pmaxr[il1] = fmaxf(pmaxr[il1], v1 + bj);
            float u0 = dl * invp[il0]; cs += u0; cm = fmaxf(cm, u0 + biasI[il0]);
            float u1 = dh * invp[il1]; cs += u1; cm = fmaxf(cm, u1 + biasI[il1]);
        }
        sRedM[ty][jl] = cm; sRedS[ty][jl] = cs;
    }
    __syncthreads();
    if (t < 32) {   // columns complete in-block (all 256 i)
        float m = -NEGF, s = 0.f;
#pragma unroll
        for (int k = 0; k < 32; k++) { m = fmaxf(m, sRedM[k][t]); s += sRedS[k][t]; }
        int j = j0 + t;
        float inv = siJ[t];
        g_mpmax1[b][j][p] = m * inv;
        g_mpmean1[b][j][p] = s * inv / fmaxf(g_len[0][b], EPSF);
    }
#pragma unroll
    for (int k = 0; k < 8; k++) {
        float m = pmaxr[k], s = psumr[k];
        for (int o = 4; o; o >>= 1) {
            m = fmaxf(m, __shfl_xor_sync(0xffffffffu, m, o));
            s += __shfl_xor_sync(0xffffffffu, s, o);
        }
        if (tx == 0) {
            int i = ty * 8 + k;
            g_rowmax[jbl][b][p][i] = m;
            g_rowsum[jbl][b][p][i] = s;
        }
    }
}

// ---------------- K6: fused maxpool + att + rowred + last (256 thr) -----------
__global__ void __launch_bounds__(256) k_mp_att(const int* mp, const int* mh) {
    __shared__ __align__(16) char sm[30336];
    int bx = blockIdx.x;
    if (bx < 1280) {
        int p = bx >> 6, rem = bx & 63;
        role_mp(p, rem >> 3, rem & 7, mp, mh, sm);
    } else if (bx < 1792) {
        int a = bx - 1280;
        role_att(a & 31, (a >> 5) & 7, a >> 8, mp, mh, sm);
    } else if (bx < 2304) {
        int a = bx - 1792;
        role_rr(a & 31, (a >> 5) & 7, a >> 8, mp, mh);
    } else {
        role_last(bx - 2304);
    }
}

// ---------------- K7: assemble 105 outputs (8 rows/block, inline mp-combine) --
__global__ void __launch_bounds__(128) k_final(float* out, const int* mp, const int* mh) {
    int side = blockIdx.z, b = blockIdx.y, i0 = blockIdx.x * 8, t = threadIdx.x;
    __shared__ float sW[60][101];
    __shared__ float sx[8][HH], sva[8][HH], svm[8][HH], sL[HH];
    __shared__ float sred[8][105];
    const float* w0 = &g_w2[0][0][0];
    const float* w2 = &g_w2[2][0][0];
    const float* w3 = &g_w2[3][0][0];
    for (int idx = t; idx < 20 * HH; idx += 128) {
        int pr = idx / HH, h = idx % HH;
        sW[pr][h] = w0[idx];
        sW[20 + pr][h] = w2[idx];
        sW[40 + pr][h] = w3[idx];
    }
    for (int idx = t; idx < 8 * HH; idx += 128) {
        int r = idx / HH, h = idx % HH;
        sx[r][h] = g_c[side][b][i0 + r][h];
        sva[r][h] = g_attmean[side][b][i0 + r][h];
        svm[r][h] = g_attmax[side][b][i0 + r][h];
    }
    if (t < HH) sL[t] = g_last[1 - side][b][t];
    __syncthreads();
    for (int o = t; o < 840; o += 128) {
        int r = o / 105, k = o % 105;
        float s = 0.f;
        if (k == 0)      { for (int h = 0; h < HH; h++) s += sx[r][h] * sL[h]; }
        else if (k == 1) { for (int h = 0; h < HH; h++) s += sx[r][h] * sva[r][h]; }
        else if (k == 2) { for (int h = 0; h < HH; h++) s += sx[r][h] * svm[r][h]; }
        else if (k == 3) { for (int h = 0; h < HH; h++) s += sva[r][h] * sva[r][h]; }
        else if (k == 4) { for (int h = 0; h < HH; h++) s += svm[r][h] * svm[r][h]; }
        else if (k < 25) { int p = k - 5;  for (int h = 0; h < HH; h++) s += sW[p][h] * sx[r][h] * sL[h]; }
        else if (k < 45) { int p = k - 25; for (int h = 0; h < HH; h++) s += sW[20 + p][h] * sx[r][h] * sva[r][h]; }
        else if (k < 65) { int p = k - 45; for (int h = 0; h < HH; h++) s += sW[20 + p][h] * sva[r][h] * sva[r][h]; }
        else if (k < 85) { int p = k - 65; for (int h = 0; h < HH; h++) s += sW[40 + p][h] * sx[r][h] * svm[r][h]; }
        else             { int p = k - 85; for (int h = 0; h < HH; h++) s += sW[40 + p][h] * svm[r][h] * svm[r][h]; }
        sred[r][k] = s;
    }
    __syncthreads();
    for (int o = t; o < 840; o += 128) {
        int r = o / 105, k = o % 105, i = i0 + r;
        float np = g_norm[side][b][i];
        float ov;
        if (k == 0)      ov = g_cmax[side][b][i];
        else if (k == 1) ov = g_cmean[side][b][i];
        else if (k == 2) ov = sred[r][0] / (fmaxf(np, EPSF) * fmaxf(g_nlast[1 - side][b], EPSF));
        else if (k < 23) {
            int p = k - 3;
            ov = sred[r][5 + p] / (fmaxf(g_npw[side][b][i][p], EPSF) * fmaxf(g_nlastw[1 - side][b][p], EPSF));
        }
        else if (k < 43) {
            int p = k - 23;
            if (side == 0) {
                float m = g_rowmax[0][b][p][i];
#pragma unroll
                for (int q = 1; q < 8; q++) m = fmaxf(m, g_rowmax[q][b][p][i]);
                float n = g_npw[0][b][i][PP + p];
                int mi = mp[b * SS + i];
                float inv = (mi && n > 0.f) ? 1.f / n : 0.f;
                ov = m * inv;
            } else ov = g_mpmax1[b][i][p];
        }
        else if (k < 63) {
            int p = k - 43;
            if (side == 0) {
                float s2 = g_rowsum[0][b][p][i];
#pragma unroll
                for (int q = 1; q < 8; q++) s2 += g_rowsum[q][b][p][i];
                float n = g_npw[0][b][i][PP + p];
                int mi = mp[b * SS + i];
                float inv = (mi && n > 0.f) ? 1.f / n : 0.f;
                ov = s2 * inv / fmaxf(g_len[1][b], EPSF);
            } else ov = g_mpmean1[b][i][p];
        }
        else if (k == 63) ov = sred[r][1] / (fmaxf(np, EPSF) * fmaxf(sqrtf(sred[r][3]), EPSF));
        else if (k < 84) {
            int p = k - 64;
            ov = sred[r][25 + p] / (fmaxf(g_npw[side][b][i][2 * PP + p], EPSF) * fmaxf(sqrtf(sred[r][45 + p]), EPSF));
        }
        else if (k == 84) ov = sred[r][2] / (fmaxf(np, EPSF) * fmaxf(sqrtf(sred[r][4]), EPSF));
        else {
            int p = k - 85;
            ov = sred[r][65 + p] / (fmaxf(g_npw[side][b][i][3 * PP + p], EPSF) * fmaxf(sqrtf(sred[r][85 + p]), EPSF));
        }
        out[((size_t)(side * BB + b) * SS + i) * 105 + k] = ov;
    }
    (void)mh;
}

// ---------------- launch ------------------------------------------------------
extern "C" void kernel_launch(void* const* d_in, const int* in_sizes, int n_in,
                              void* d_out, int out_size) {
    const float* ctx_p = (const float*)d_in[0];
    const int*   mp    = (const int*)d_in[1];
    const float* ctx_h = (const float*)d_in[2];
    const int*   mh    = (const int*)d_in[3];
    const float* wf    = (const float*)d_in[4];
    const float* wm    = (const float*)d_in[5];
    const float* wa    = (const float*)d_in[6];
    const float* wx    = (const float*)d_in[7];
    float* out = (float*)d_out;

    k_w2<<<6, 256>>>(wf, wm, wa, wx, mp, mh);
    k_prep1<<<dim3(BB * SS, 2), 128>>>(ctx_p, mp, ctx_h, mh);
    k_cos_prep2<<<768, 128>>>();
    k_mp_att<<<2306, 256>>>(mp, mh);
    k_final<<<dim3(32, BB, 2), 128>>>(out, mp, mh);
}